// round 6
// baseline (speedup 1.0000x reference)
#include <cuda_runtime.h>
#include <math.h>

// Problem dims
#define BB_ 16
#define T_ 64
#define S_ 32
#define F_ 128
#define H_ 128
#define NH_ 4

// ---------------- scratch (no allocations allowed) ----------------
__device__ float g_q[BB_*NH_*H_*S_];     // 262144
__device__ float g_k[BB_*NH_*H_*S_];
__device__ float g_v[BB_*NH_*H_*S_];
__device__ float g_att4[BB_*NH_*H_*S_];
__device__ float g_a[BB_*H_*S_];         // 65536
__device__ float g_part[3*16*BB_*H_];    // 98304
__device__ float g_h2[BB_*H_];           // 2048

__device__ __forceinline__ unsigned int rotl32_(unsigned int v, int d){ return (v << d) | (v >> (32 - d)); }

// Neumaier compensated accumulate: s += p with running compensation c.
__device__ __forceinline__ void kadd_(float& s, float& c, float p){
  float t = s + p;
  c += (fabsf(s) >= fabsf(p)) ? ((s - t) + p) : ((p - t) + s);
  s = t;
}

// Exact JAX threefry2x32 (20 rounds), key = (k0, k1)
__device__ __forceinline__ void threefry2x32_(unsigned int k0, unsigned int k1,
    unsigned int c0, unsigned int c1, unsigned int& o0, unsigned int& o1)
{
  unsigned int ks2 = k0 ^ k1 ^ 0x1BD11BDAu;
  unsigned int x0 = c0 + k0, x1 = c1 + k1;
  const int ra[4] = {13,15,26,6};
  const int rb[4] = {17,29,16,24};
  #pragma unroll
  for (int i=0;i<4;i++){ x0 += x1; x1 = rotl32_(x1, ra[i]); x1 ^= x0; }
  x0 += k1; x1 += ks2 + 1u;
  #pragma unroll
  for (int i=0;i<4;i++){ x0 += x1; x1 = rotl32_(x1, rb[i]); x1 ^= x0; }
  x0 += ks2; x1 += k0 + 2u;
  #pragma unroll
  for (int i=0;i<4;i++){ x0 += x1; x1 = rotl32_(x1, ra[i]); x1 ^= x0; }
  x0 += k0; x1 += k1 + 3u;
  #pragma unroll
  for (int i=0;i<4;i++){ x0 += x1; x1 = rotl32_(x1, rb[i]); x1 ^= x0; }
  x0 += k1; x1 += ks2 + 4u;
  #pragma unroll
  for (int i=0;i<4;i++){ x0 += x1; x1 = rotl32_(x1, ra[i]); x1 ^= x0; }
  x0 += ks2; x1 += k0 + 5u;
  o0 = x0; o1 = x1;
}

// ---------------- K1: encoder front (hid + q/k/v per (b, head)) ----------------
// Only the t = T-1 slice of the input matters (h[:, -1] is the sole consumer).
__global__ void __launch_bounds__(256) qkv_kernel(
    const float* __restrict__ xsrc,
    const float* __restrict__ w_enc, const float* __restrict__ b_enc,
    const float* __restrict__ wq, const float* __restrict__ bq,
    const float* __restrict__ wk, const float* __restrict__ bk,
    const float* __restrict__ wv, const float* __restrict__ bv)
{
  __shared__ float xs[S_*129];        // padded: bank-conflict-free column reads
  __shared__ float hid[H_*S_];
  __shared__ float wqn[S_*33], wkn[S_*33], wvn[S_*33];
  int b = blockIdx.x >> 2, n = blockIdx.x & 3;
  int tid = threadIdx.x;
  const float* xb = xsrc + (size_t)b*(T_*S_*F_) + (size_t)(T_-1)*(S_*F_);

  for (int i = tid; i < S_*F_; i += 256) {
    int s = i >> 7, f = i & 127;
    xs[s*129+f] = xb[i];
  }
  for (int i = tid; i < S_*S_; i += 256) {
    int sp = i >> 5, s = i & 31;
    wqn[sp*33+s] = wq[sp*(S_*NH_) + n*S_ + s];
    wkn[sp*33+s] = wk[sp*(S_*NH_) + n*S_ + s];
    wvn[sp*33+s] = wv[sp*(S_*NH_) + n*S_ + s];
  }
  __syncthreads();

  // hid[h][s] = x[s,:] . w_enc[:,h] + b_enc[h]   (transposed layout), compensated
  for (int i = tid; i < H_*S_; i += 256) {
    int h = i >> 5, s = i & 31;
    float acc = 0.f, cc = 0.f;
    #pragma unroll 8
    for (int f = 0; f < F_; f++)
      kadd_(acc, cc, xs[s*129+f] * w_enc[f*H_ + h]);
    hid[h*S_ + s] = (acc + cc) + b_enc[h];
  }
  __syncthreads();

  const float scale = 0.08838834764831845f; // 1/sqrt(H)
  size_t base = ((size_t)(b*NH_ + n))*(H_*S_);
  for (int i = tid; i < H_*S_; i += 256) {
    int h = i >> 5, s = i & 31;
    float aq = 0.f, cq = 0.f, ak = 0.f, ck = 0.f, av = 0.f, cv = 0.f;
    #pragma unroll
    for (int sp = 0; sp < S_; sp++) {
      float hv = hid[h*S_+sp];
      kadd_(aq, cq, hv * wqn[sp*33+s]);
      kadd_(ak, ck, hv * wkn[sp*33+s]);
      kadd_(av, cv, hv * wvn[sp*33+s]);
    }
    g_q[base + i] = ((aq + cq) + bq[n*S_+s]) * scale;
    g_k[base + i] = (ak + ck) + bk[n*S_+s];
    g_v[base + i] = (av + cv) + bv[n*S_+s];
  }
}

// ---------------- K2: attention (softmax over g=H, per (b,n, 32 q-rows)) ----------------
__global__ void __launch_bounds__(256) attn_kernel()
{
  __shared__ float ksm[H_*33];
  __shared__ float vsm[H_*33];
  __shared__ float qsm[32*33];
  __shared__ float prob[8*128];
  int blk = blockIdx.x;          // (b*4+n)*4 + hq
  int bn = blk >> 2, hq = blk & 3;
  int tid = threadIdx.x;
  size_t base = (size_t)bn * (H_*S_);
  for (int i = tid; i < H_*S_; i += 256) {
    ksm[(i>>5)*33 + (i&31)] = g_k[base + i];
    vsm[(i>>5)*33 + (i&31)] = g_v[base + i];
  }
  for (int i = tid; i < 32*S_; i += 256) {
    qsm[(i>>5)*33 + (i&31)] = g_q[base + (size_t)hq*32*S_ + i];
  }
  __syncthreads();
  int warp = tid >> 5, lane = tid & 31;
  float* pw = prob + warp*128;
  #pragma unroll
  for (int r = 0; r < 4; r++) {
    int hh = warp*4 + r;
    float lg[4];
    #pragma unroll
    for (int j = 0; j < 4; j++) {
      int g = lane + 32*j;
      float acc = 0.f, cc = 0.f;
      #pragma unroll
      for (int s = 0; s < S_; s++)
        kadd_(acc, cc, qsm[hh*33+s] * ksm[g*33+s]);
      lg[j] = acc + cc;
    }
    float m = fmaxf(fmaxf(lg[0],lg[1]), fmaxf(lg[2],lg[3]));
    #pragma unroll
    for (int o = 16; o; o >>= 1) m = fmaxf(m, __shfl_xor_sync(0xffffffffu, m, o));
    float ssum = 0.f;
    #pragma unroll
    for (int j = 0; j < 4; j++){ lg[j] = expf(lg[j]-m); ssum += lg[j]; }
    #pragma unroll
    for (int o = 16; o; o >>= 1) ssum += __shfl_xor_sync(0xffffffffu, ssum, o);
    float inv = 1.f/ssum;
    #pragma unroll
    for (int j = 0; j < 4; j++) pw[lane + 32*j] = lg[j]*inv;
    __syncwarp();
    float acc = 0.f, cc = 0.f;
    #pragma unroll 8
    for (int g = 0; g < H_; g++)
      kadd_(acc, cc, pw[g] * vsm[g*33+lane]);
    g_att4[base + (size_t)(hq*32+hh)*S_ + lane] = acc + cc;
    __syncwarp();
  }
}

// ---------------- K3: head mean + ReLU ----------------
__global__ void combine_kernel()
{
  int i = blockIdx.x*256 + threadIdx.x; // < 65536
  int b = i >> 12, hs = i & 4095;
  size_t bb = (size_t)b*4*(H_*S_);
  float v = (g_att4[bb + hs] + g_att4[bb + 4096 + hs])
          + (g_att4[bb + 8192 + hs] + g_att4[bb + 12288 + hs]);
  v *= 0.25f;
  g_a[i] = v > 0.f ? v : 0.f;
}

// ---------------- K4: gate GEMM, split-K (c0 = 0 => only i,g,o gates; rows [0,4096)) ----
__global__ void __launch_bounds__(256) gates_kernel(
    const float* __restrict__ Wii, const float* __restrict__ Wig, const float* __restrict__ Wio)
{
  __shared__ float as[16*256];
  int gate = blockIdx.x >> 4, chunk = blockIdx.x & 15;
  const float* Wm = (gate == 0) ? Wii : (gate == 1) ? Wig : Wio;
  int tid = threadIdx.x;
  int j0 = chunk*256;
  for (int i = tid; i < 16*256; i += 256) {
    int bb = i >> 8, j = i & 255;
    as[bb*256 + j] = g_a[bb*4096 + j0 + j];
  }
  __syncthreads();
  int m = tid & 127, half = tid >> 7;
  float acc[8] = {0.f,0.f,0.f,0.f,0.f,0.f,0.f,0.f};
  float cmp[8] = {0.f,0.f,0.f,0.f,0.f,0.f,0.f,0.f};
  #pragma unroll 2
  for (int j = 0; j < 256; j++) {
    float w = Wm[(size_t)(j0+j)*H_ + m];
    #pragma unroll
    for (int bb = 0; bb < 8; bb++)
      kadd_(acc[bb], cmp[bb], as[(half*8+bb)*256 + j] * w);
  }
  #pragma unroll
  for (int bb = 0; bb < 8; bb++)
    g_part[((gate*16 + chunk)*16 + half*8 + bb)*H_ + m] = acc[bb] + cmp[bb];
}

// ---------------- K5: gate reduce + LSTM cell + fc + reparam + KL ----------------
__global__ void __launch_bounds__(256) head_kernel(
    const float* __restrict__ w_fc, const float* __restrict__ b_fc,
    unsigned int keylo, float* __restrict__ z_out, float* __restrict__ kl_out)
{
  __shared__ float sm1[3*2048];
  __shared__ float hb[2048];
  __shared__ double redd[256];
  int tid = threadIdx.x;
  // reduce split-K chunks (compensated)
  for (int idx = tid; idx < 3*2048; idx += 256) {
    int gate = idx >> 11, r = idx & 2047;
    float s = 0.f, c = 0.f;
    #pragma unroll
    for (int ch = 0; ch < 16; ch++)
      kadd_(s, c, g_part[(gate*16 + ch)*2048 + r]);
    sm1[idx] = s + c;
  }
  __syncthreads();
  // LSTM cell in double (c0 = 0 => c = i*g)
  for (int idx = tid; idx < 2048; idx += 256) {
    double iv = 1.0/(1.0 + exp(-(double)sm1[idx]));
    double gv = tanh((double)sm1[2048 + idx]);
    double ov = 1.0/(1.0 + exp(-(double)sm1[4096 + idx]));
    hb[idx] = (float)(ov * tanh(iv * gv));
  }
  __syncthreads();
  // out[b][c] = h[b,:] @ w_fc[:,c] + b_fc[c] (compensated) -> reuse sm1
  for (int idx = tid; idx < 4096; idx += 256) {
    int bb = idx >> 8, c = idx & 255;
    float s = 0.f, cc = 0.f;
    #pragma unroll 8
    for (int mm = 0; mm < 128; mm++)
      kadd_(s, cc, hb[bb*128 + mm] * w_fc[mm*256 + c]);
    sm1[idx] = (s + cc) + b_fc[c];
  }
  __syncthreads();
  double kacc = 0.0;
  for (int idx = tid; idx < 2048; idx += 256) {
    int bb = idx >> 7, k = idx & 127;
    float mu = sm1[bb*256 + k];
    float lv = sm1[bb*256 + 128 + k];
    // eps via JAX partitionable threefry: counter=(0, idx), key=(0, seed), bits = o0^o1
    unsigned int o0, o1;
    threefry2x32_(0u, keylo, 0u, (unsigned int)idx, o0, o1);
    unsigned int bits = o0 ^ o1;
    float f = __uint_as_float((bits >> 9) | 0x3f800000u) - 1.0f;   // [0,1)
    const float lo = -0.99999994f;                                 // nextafter(-1,0)
    float u = fmaxf(lo, fmaf(f, 2.0f, lo));                        // (1 - lo) rounds to 2.0f
    float eps = 1.4142135623730951f * erfinvf(u);
    z_out[idx] = fmaf(eps, expf(0.5f*lv), mu);
    double dmu = (double)mu, dlv = (double)lv;
    kacc += 1.0 + dlv - dmu*dmu - exp(dlv);
  }
  redd[tid] = kacc;
  __syncthreads();
  for (int o = 128; o; o >>= 1) {
    if (tid < o) redd[tid] += redd[tid + o];
    __syncthreads();
  }
  if (tid == 0) kl_out[0] = (float)(-0.5 * redd[0] * (1.0/2048.0));
}

// ---------------- K6: decode MLP (z -> h1 -> h2), compensated ----------------
__global__ void __launch_bounds__(256) dec_small_kernel(
    const float* __restrict__ z,
    const float* __restrict__ w_d1, const float* __restrict__ b_d1,
    const float* __restrict__ w_d2, const float* __restrict__ b_d2)
{
  __shared__ float zb[2048], h1[2048];
  int tid = threadIdx.x;
  for (int i = tid; i < 2048; i += 256) zb[i] = z[i];
  __syncthreads();
  for (int i = tid; i < 2048; i += 256) {
    int bb = i >> 7, c = i & 127;
    float s = 0.f, cc = 0.f;
    #pragma unroll 8
    for (int j = 0; j < 128; j++)
      kadd_(s, cc, zb[bb*128+j] * w_d1[j*128+c]);
    float acc = (s + cc) + b_d1[c];
    h1[i] = fmaxf(acc, 0.f);
  }
  __syncthreads();
  for (int i = tid; i < 2048; i += 256) {
    int bb = i >> 7, c = i & 127;
    float s = 0.f, cc = 0.f;
    #pragma unroll 8
    for (int j = 0; j < 128; j++)
      kadd_(s, cc, h1[bb*128+j] * w_d2[j*128+c]);
    float acc = (s + cc) + b_d2[c];
    g_h2[i] = fmaxf(acc, 0.f);
  }
}

// ---------------- K7: big decode GEMM h2[16,128] @ w_d3[128,262144] + b_d3 ----------------
// Memory-bound (134 MB of w_d3). Batch pairs packed into f32x2 so the FMA pipe
// keeps up with HBM (dual-FP32 fma.rn.f32x2).
__device__ __forceinline__ unsigned long long pk2_(float a, float b){
  return (unsigned long long)__float_as_uint(a) | ((unsigned long long)__float_as_uint(b) << 32);
}

__global__ void __launch_bounds__(256) big_kernel(
    const float* __restrict__ w_d3, const float* __restrict__ b_d3, float* __restrict__ out)
{
  __shared__ unsigned long long hp[8*128];   // (b-pair, j) packed h2 values
  int tid = threadIdx.x;
  for (int i = tid; i < 1024; i += 256) {
    int p = i >> 7, j = i & 127;
    hp[i] = pk2_(g_h2[(2*p)*128 + j], g_h2[(2*p+1)*128 + j]);
  }
  __syncthreads();
  size_t m2 = (size_t)blockIdx.x*256 + tid;    // float2 column index, < 131072
  const float2* w2 = (const float2*)w_d3;
  float2 bv2 = ((const float2*)b_d3)[m2];
  unsigned long long accx[8], accy[8];
  unsigned long long bx = pk2_(bv2.x, bv2.x), by = pk2_(bv2.y, bv2.y);
  #pragma unroll
  for (int p = 0; p < 8; p++){ accx[p] = bx; accy[p] = by; }
  #pragma unroll 4
  for (int j = 0; j < 128; j++) {
    float2 w = __ldg(&w2[(size_t)j*131072 + m2]);
    unsigned long long wx = pk2_(w.x, w.x), wy = pk2_(w.y, w.y);
    #pragma unroll
    for (int p = 0; p < 8; p++) {
      unsigned long long hpair = hp[p*128 + j];
      asm("fma.rn.f32x2 %0, %1, %2, %3;" : "=l"(accx[p]) : "l"(hpair), "l"(wx), "l"(accx[p]));
      asm("fma.rn.f32x2 %0, %1, %2, %3;" : "=l"(accy[p]) : "l"(hpair), "l"(wy), "l"(accy[p]));
    }
  }
  float2* o2 = (float2*)out;
  #pragma unroll
  for (int p = 0; p < 8; p++) {
    float2 v0, v1;
    v0.x = __uint_as_float((unsigned int)accx[p]);
    v0.y = __uint_as_float((unsigned int)accy[p]);
    v1.x = __uint_as_float((unsigned int)(accx[p] >> 32));
    v1.y = __uint_as_float((unsigned int)(accy[p] >> 32));
    o2[(size_t)(2*p)*131072 + m2]   = v0;
    o2[(size_t)(2*p+1)*131072 + m2] = v1;
  }
}

// ---------------- launcher ----------------
extern "C" void kernel_launch(void* const* d_in, const int* in_sizes, int n_in,
                              void* d_out, int out_size)
{
  (void)in_sizes; (void)n_in; (void)out_size;
  const float* x     = (const float*)d_in[0];
  const float* w_enc = (const float*)d_in[1];
  const float* b_enc = (const float*)d_in[2];
  const float* wq    = (const float*)d_in[3];
  const float* bq    = (const float*)d_in[4];
  const float* wk    = (const float*)d_in[5];
  const float* bk    = (const float*)d_in[6];
  const float* wv    = (const float*)d_in[7];
  const float* bv    = (const float*)d_in[8];
  const float* W_ii  = (const float*)d_in[9];
  const float* W_ig  = (const float*)d_in[13];
  const float* W_io  = (const float*)d_in[15];
  const float* w_fc  = (const float*)d_in[17];
  const float* b_fc  = (const float*)d_in[18];
  const float* w_d1  = (const float*)d_in[19];
  const float* b_d1  = (const float*)d_in[20];
  const float* w_d2  = (const float*)d_in[21];
  const float* b_d2  = (const float*)d_in[22];
  const float* w_d3  = (const float*)d_in[23];
  const float* b_d3  = (const float*)d_in[24];

  float* outp = (float*)d_out;
  float* xhat = outp;                  // [16,64,32,128] = 4194304
  float* z1   = outp + 4194304;        // [16,128]
  float* z2   = z1 + 2048;             // [16,128]
  float* kl1  = z2 + 2048;             // scalar
  float* kl2  = kl1 + 1;               // scalar

  // -------- pass 1: encode(x, key=1) --------
  qkv_kernel<<<64, 256>>>(x, w_enc, b_enc, wq, bq, wk, bk, wv, bv);
  attn_kernel<<<256, 256>>>();
  combine_kernel<<<256, 256>>>();
  gates_kernel<<<48, 256>>>(W_ii, W_ig, W_io);
  head_kernel<<<1, 256>>>(w_fc, b_fc, 1u, z1, kl1);
  // -------- decode(z1) --------
  dec_small_kernel<<<1, 256>>>(z1, w_d1, b_d1, w_d2, b_d2);
  big_kernel<<<512, 256>>>(w_d3, b_d3, xhat);
  // -------- pass 2: encode(x_hat1, key=2) --------
  qkv_kernel<<<64, 256>>>(xhat, w_enc, b_enc, wq, bq, wk, bk, wv, bv);
  attn_kernel<<<256, 256>>>();
  combine_kernel<<<256, 256>>>();
  gates_kernel<<<48, 256>>>(W_ii, W_ig, W_io);
  head_kernel<<<1, 256>>>(w_fc, b_fc, 2u, z2, kl2);
}

// round 7
// speedup vs baseline: 2.1043x; 2.1043x over previous
#include <cuda_runtime.h>
#include <math.h>

// Problem dims
#define BB_ 16
#define T_ 64
#define S_ 32
#define F_ 128
#define H_ 128
#define NH_ 4

// ---------------- scratch (no allocations allowed) ----------------
__device__ float g_hid[BB_*H_*S_];       // 65536   hid (t=T-1 slice), per batch
__device__ float g_q[BB_*NH_*H_*S_];     // 262144
__device__ float g_k[BB_*NH_*H_*S_];
__device__ float g_v[BB_*NH_*H_*S_];
__device__ float g_att4[BB_*NH_*H_*S_];
__device__ float g_a[BB_*H_*S_];         // 65536
__device__ float g_part[3*32*BB_*H_];    // 196608  gate split-K partials
__device__ float g_gsum[3*BB_*H_];       // 6144    reduced gate pre-activations
__device__ float g_h[BB_*H_];            // 2048    LSTM h
__device__ float g_fc[BB_*2*H_];         // 4096    fc out (mu|logvar)
__device__ float g_h2[BB_*H_];           // 2048    decoder h2

__device__ __forceinline__ unsigned int rotl32_(unsigned int v, int d){ return (v << d) | (v >> (32 - d)); }

// Neumaier compensated accumulate: s += p with running compensation c.
__device__ __forceinline__ void kadd_(float& s, float& c, float p){
  float t = s + p;
  c += (fabsf(s) >= fabsf(p)) ? ((s - t) + p) : ((p - t) + s);
  s = t;
}

// Exact JAX threefry2x32 (20 rounds), key = (k0, k1)
__device__ __forceinline__ void threefry2x32_(unsigned int k0, unsigned int k1,
    unsigned int c0, unsigned int c1, unsigned int& o0, unsigned int& o1)
{
  unsigned int ks2 = k0 ^ k1 ^ 0x1BD11BDAu;
  unsigned int x0 = c0 + k0, x1 = c1 + k1;
  const int ra[4] = {13,15,26,6};
  const int rb[4] = {17,29,16,24};
  #pragma unroll
  for (int i=0;i<4;i++){ x0 += x1; x1 = rotl32_(x1, ra[i]); x1 ^= x0; }
  x0 += k1; x1 += ks2 + 1u;
  #pragma unroll
  for (int i=0;i<4;i++){ x0 += x1; x1 = rotl32_(x1, rb[i]); x1 ^= x0; }
  x0 += ks2; x1 += k0 + 2u;
  #pragma unroll
  for (int i=0;i<4;i++){ x0 += x1; x1 = rotl32_(x1, ra[i]); x1 ^= x0; }
  x0 += k0; x1 += k1 + 3u;
  #pragma unroll
  for (int i=0;i<4;i++){ x0 += x1; x1 = rotl32_(x1, rb[i]); x1 ^= x0; }
  x0 += k1; x1 += ks2 + 4u;
  #pragma unroll
  for (int i=0;i<4;i++){ x0 += x1; x1 = rotl32_(x1, ra[i]); x1 ^= x0; }
  x0 += ks2; x1 += k0 + 5u;
  o0 = x0; o1 = x1;
}

// ---------------- K1a: hid[h][s] per batch (t = T-1 slice only) ----------------
// grid 64: (b, h-tile of 32). hid computed ONCE per batch (was 4x redundant).
__global__ void __launch_bounds__(256) hid_kernel(
    const float* __restrict__ xsrc,
    const float* __restrict__ w_enc, const float* __restrict__ b_enc)
{
  __shared__ float xs[S_*129];
  int b = blockIdx.x >> 2, ht = blockIdx.x & 3;
  int tid = threadIdx.x;
  const float* xb = xsrc + (size_t)b*(T_*S_*F_) + (size_t)(T_-1)*(S_*F_);
  for (int i = tid; i < S_*F_; i += 256) {
    int s = i >> 7, f = i & 127;
    xs[s*129+f] = xb[i];
  }
  __syncthreads();
  for (int i = tid; i < 32*S_; i += 256) {
    int hl = i >> 5, s = i & 31;
    int h = ht*32 + hl;
    float acc = 0.f, cc = 0.f;
    #pragma unroll 8
    for (int f = 0; f < F_; f++)
      kadd_(acc, cc, xs[s*129+f] * w_enc[f*H_ + h]);
    g_hid[b*(H_*S_) + h*S_ + s] = (acc + cc) + b_enc[h];
  }
}

// ---------------- K1b: q/k/v head projections ----------------
// grid 256: (b, n, h-tile of 32).
__global__ void __launch_bounds__(256) heads_kernel(
    const float* __restrict__ wq, const float* __restrict__ bq,
    const float* __restrict__ wk, const float* __restrict__ bk,
    const float* __restrict__ wv, const float* __restrict__ bv)
{
  __shared__ float hsm[32*33];
  __shared__ float wqn[S_*33], wkn[S_*33], wvn[S_*33];
  int b = blockIdx.x >> 4, n = (blockIdx.x >> 2) & 3, ht = blockIdx.x & 3;
  int tid = threadIdx.x;
  for (int i = tid; i < 32*S_; i += 256) {
    int hl = i >> 5, s = i & 31;
    hsm[hl*33+s] = g_hid[b*(H_*S_) + (ht*32+hl)*S_ + s];
  }
  for (int i = tid; i < S_*S_; i += 256) {
    int sp = i >> 5, s = i & 31;
    wqn[sp*33+s] = wq[sp*(S_*NH_) + n*S_ + s];
    wkn[sp*33+s] = wk[sp*(S_*NH_) + n*S_ + s];
    wvn[sp*33+s] = wv[sp*(S_*NH_) + n*S_ + s];
  }
  __syncthreads();
  const float scale = 0.08838834764831845f; // 1/sqrt(H)
  size_t base = ((size_t)(b*NH_ + n))*(H_*S_);
  for (int i = tid; i < 32*S_; i += 256) {
    int hl = i >> 5, s = i & 31;
    float aq = 0.f, cq = 0.f, ak = 0.f, ck = 0.f, av = 0.f, cv = 0.f;
    #pragma unroll
    for (int sp = 0; sp < S_; sp++) {
      float hv = hsm[hl*33+sp];
      kadd_(aq, cq, hv * wqn[sp*33+s]);
      kadd_(ak, ck, hv * wkn[sp*33+s]);
      kadd_(av, cv, hv * wvn[sp*33+s]);
    }
    size_t o = base + (size_t)(ht*32+hl)*S_ + s;
    g_q[o] = ((aq + cq) + bq[n*S_+s]) * scale;
    g_k[o] = (ak + ck) + bk[n*S_+s];
    g_v[o] = (av + cv) + bv[n*S_+s];
  }
}

// ---------------- K2: attention (softmax over g=H, per (b,n, 32 q-rows)) ----------------
__global__ void __launch_bounds__(256) attn_kernel()
{
  __shared__ float ksm[H_*33];
  __shared__ float vsm[H_*33];
  __shared__ float qsm[32*33];
  __shared__ float prob[8*128];
  int blk = blockIdx.x;          // (b*4+n)*4 + hq
  int bn = blk >> 2, hq = blk & 3;
  int tid = threadIdx.x;
  size_t base = (size_t)bn * (H_*S_);
  for (int i = tid; i < H_*S_; i += 256) {
    ksm[(i>>5)*33 + (i&31)] = g_k[base + i];
    vsm[(i>>5)*33 + (i&31)] = g_v[base + i];
  }
  for (int i = tid; i < 32*S_; i += 256) {
    qsm[(i>>5)*33 + (i&31)] = g_q[base + (size_t)hq*32*S_ + i];
  }
  __syncthreads();
  int warp = tid >> 5, lane = tid & 31;
  float* pw = prob + warp*128;
  #pragma unroll
  for (int r = 0; r < 4; r++) {
    int hh = warp*4 + r;
    float lg[4];
    #pragma unroll
    for (int j = 0; j < 4; j++) {
      int g = lane + 32*j;
      float acc = 0.f, cc = 0.f;
      #pragma unroll
      for (int s = 0; s < S_; s++)
        kadd_(acc, cc, qsm[hh*33+s] * ksm[g*33+s]);
      lg[j] = acc + cc;
    }
    float m = fmaxf(fmaxf(lg[0],lg[1]), fmaxf(lg[2],lg[3]));
    #pragma unroll
    for (int o = 16; o; o >>= 1) m = fmaxf(m, __shfl_xor_sync(0xffffffffu, m, o));
    float ssum = 0.f;
    #pragma unroll
    for (int j = 0; j < 4; j++){ lg[j] = expf(lg[j]-m); ssum += lg[j]; }
    #pragma unroll
    for (int o = 16; o; o >>= 1) ssum += __shfl_xor_sync(0xffffffffu, ssum, o);
    float inv = 1.f/ssum;
    #pragma unroll
    for (int j = 0; j < 4; j++) pw[lane + 32*j] = lg[j]*inv;
    __syncwarp();
    float acc = 0.f, cc = 0.f;
    #pragma unroll 8
    for (int g = 0; g < H_; g++)
      kadd_(acc, cc, pw[g] * vsm[g*33+lane]);
    g_att4[base + (size_t)(hq*32+hh)*S_ + lane] = acc + cc;
    __syncwarp();
  }
}

// ---------------- K3: head mean + ReLU ----------------
__global__ void combine_kernel()
{
  int i = blockIdx.x*256 + threadIdx.x; // < 65536
  int b = i >> 12, hs = i & 4095;
  size_t bb = (size_t)b*4*(H_*S_);
  float v = (g_att4[bb + hs] + g_att4[bb + 4096 + hs])
          + (g_att4[bb + 8192 + hs] + g_att4[bb + 12288 + hs]);
  v *= 0.25f;
  g_a[i] = v > 0.f ? v : 0.f;
}

// ---------------- K4: gate GEMM, split-K (c0=0 => only i,g,o gates; rows [0,4096)) ----
// grid 192: gate(3) x chunk(32 of 128) x batch-half(2). 4 accumulators/thread.
__global__ void __launch_bounds__(256) gates_kernel(
    const float* __restrict__ Wii, const float* __restrict__ Wig, const float* __restrict__ Wio)
{
  __shared__ float as[8*128];
  int gate = blockIdx.x / 64;
  int rem  = blockIdx.x - gate*64;
  int chunk = rem >> 1, bh = rem & 1;
  const float* Wm = (gate == 0) ? Wii : (gate == 1) ? Wig : Wio;
  int tid = threadIdx.x;
  int j0 = chunk*128;
  for (int i = tid; i < 8*128; i += 256) {
    int bb = i >> 7, j = i & 127;
    as[i] = g_a[(bh*8 + bb)*4096 + j0 + j];
  }
  __syncthreads();
  int m = tid & 127, half = tid >> 7;
  float acc[4] = {0.f,0.f,0.f,0.f};
  float cmp[4] = {0.f,0.f,0.f,0.f};
  #pragma unroll 2
  for (int j = 0; j < 128; j++) {
    float w = Wm[(size_t)(j0+j)*H_ + m];
    #pragma unroll
    for (int bb = 0; bb < 4; bb++)
      kadd_(acc[bb], cmp[bb], as[(half*4+bb)*128 + j] * w);
  }
  size_t cbase = ((size_t)(gate*32 + chunk))*(BB_*H_);
  #pragma unroll
  for (int bb = 0; bb < 4; bb++)
    g_part[cbase + (bh*8 + half*4 + bb)*H_ + m] = acc[bb] + cmp[bb];
}

// ---------------- K5a: reduce split-K chunks (compensated) ----------------
__global__ void __launch_bounds__(256) reduce_kernel()
{
  int idx = blockIdx.x*256 + threadIdx.x;   // < 6144
  int gate = idx >> 11, r = idx & 2047;
  float s = 0.f, c = 0.f;
  #pragma unroll
  for (int ch = 0; ch < 32; ch++)
    kadd_(s, c, g_part[(size_t)(gate*32 + ch)*(BB_*H_) + r]);
  g_gsum[idx] = s + c;
}

// ---------------- K5b: LSTM cell in double (c0 = 0 => c = i*g) ----------------
__global__ void __launch_bounds__(256) lstm_kernel()
{
  int idx = blockIdx.x*256 + threadIdx.x;   // < 2048
  double iv = 1.0/(1.0 + exp(-(double)g_gsum[idx]));
  double gv = tanh((double)g_gsum[2048 + idx]);
  double ov = 1.0/(1.0 + exp(-(double)g_gsum[4096 + idx]));
  g_h[idx] = (float)(ov * tanh(iv * gv));
}

// ---------------- K5c: fc — out[b][c] = h[b,:] @ w_fc[:,c] + b_fc[c] ----------------
// grid 16: one batch row per block; h row cached in smem.
__global__ void __launch_bounds__(256) fc_kernel(
    const float* __restrict__ w_fc, const float* __restrict__ b_fc)
{
  __shared__ float hrow[128];
  int bb = blockIdx.x, c = threadIdx.x;   // c < 256
  if (c < 128) hrow[c] = g_h[bb*128 + c];
  __syncthreads();
  float s = 0.f, cc = 0.f;
  #pragma unroll 8
  for (int mm = 0; mm < 128; mm++)
    kadd_(s, cc, hrow[mm] * w_fc[mm*256 + c]);
  g_fc[bb*256 + c] = (s + cc) + b_fc[c];
}

// ---------------- K5d: reparam + KL ----------------
__global__ void __launch_bounds__(256) kl_kernel(
    unsigned int keylo, float* __restrict__ z_out, float* __restrict__ kl_out)
{
  __shared__ double redd[256];
  int tid = threadIdx.x;
  double kacc = 0.0;
  for (int idx = tid; idx < 2048; idx += 256) {
    int bb = idx >> 7, k = idx & 127;
    float mu = g_fc[bb*256 + k];
    float lv = g_fc[bb*256 + 128 + k];
    // eps via JAX partitionable threefry: counter=(0, idx), key=(0, seed), bits = o0^o1
    unsigned int o0, o1;
    threefry2x32_(0u, keylo, 0u, (unsigned int)idx, o0, o1);
    unsigned int bits = o0 ^ o1;
    float f = __uint_as_float((bits >> 9) | 0x3f800000u) - 1.0f;   // [0,1)
    const float lo = -0.99999994f;                                 // nextafter(-1,0)
    float u = fmaxf(lo, fmaf(f, 2.0f, lo));                        // (1 - lo) rounds to 2.0f
    float eps = 1.4142135623730951f * erfinvf(u);
    z_out[idx] = fmaf(eps, expf(0.5f*lv), mu);
    double dmu = (double)mu, dlv = (double)lv;
    kacc += 1.0 + dlv - dmu*dmu - exp(dlv);
  }
  redd[tid] = kacc;
  __syncthreads();
  for (int o = 128; o; o >>= 1) {
    if (tid < o) redd[tid] += redd[tid + o];
    __syncthreads();
  }
  if (tid == 0) kl_out[0] = (float)(-0.5 * redd[0] * (1.0/2048.0));
}

// ---------------- K6: decode MLP (z -> h1 -> h2), compensated ----------------
__global__ void __launch_bounds__(256) dec_small_kernel(
    const float* __restrict__ z,
    const float* __restrict__ w_d1, const float* __restrict__ b_d1,
    const float* __restrict__ w_d2, const float* __restrict__ b_d2)
{
  __shared__ float zb[2048], h1[2048];
  int tid = threadIdx.x;
  for (int i = tid; i < 2048; i += 256) zb[i] = z[i];
  __syncthreads();
  for (int i = tid; i < 2048; i += 256) {
    int bb = i >> 7, c = i & 127;
    float s = 0.f, cc = 0.f;
    #pragma unroll 8
    for (int j = 0; j < 128; j++)
      kadd_(s, cc, zb[bb*128+j] * w_d1[j*128+c]);
    float acc = (s + cc) + b_d1[c];
    h1[i] = fmaxf(acc, 0.f);
  }
  __syncthreads();
  for (int i = tid; i < 2048; i += 256) {
    int bb = i >> 7, c = i & 127;
    float s = 0.f, cc = 0.f;
    #pragma unroll 8
    for (int j = 0; j < 128; j++)
      kadd_(s, cc, h1[bb*128+j] * w_d2[j*128+c]);
    float acc = (s + cc) + b_d2[c];
    g_h2[i] = fmaxf(acc, 0.f);
  }
}

// ---------------- K7: big decode GEMM h2[16,128] @ w_d3[128,262144] + b_d3 ----------------
// Memory-bound (134 MB of w_d3). Batch pairs packed into f32x2 so the FMA pipe
// keeps up with HBM (dual-FP32 fma.rn.f32x2).
__device__ __forceinline__ unsigned long long pk2_(float a, float b){
  return (unsigned long long)__float_as_uint(a) | ((unsigned long long)__float_as_uint(b) << 32);
}

__global__ void __launch_bounds__(256) big_kernel(
    const float* __restrict__ w_d3, const float* __restrict__ b_d3, float* __restrict__ out)
{
  __shared__ unsigned long long hp[8*128];   // (b-pair, j) packed h2 values
  int tid = threadIdx.x;
  for (int i = tid; i < 1024; i += 256) {
    int p = i >> 7, j = i & 127;
    hp[i] = pk2_(g_h2[(2*p)*128 + j], g_h2[(2*p+1)*128 + j]);
  }
  __syncthreads();
  size_t m2 = (size_t)blockIdx.x*256 + tid;    // float2 column index, < 131072
  const float2* w2 = (const float2*)w_d3;
  float2 bv2 = ((const float2*)b_d3)[m2];
  unsigned long long accx[8], accy[8];
  unsigned long long bx = pk2_(bv2.x, bv2.x), by = pk2_(bv2.y, bv2.y);
  #pragma unroll
  for (int p = 0; p < 8; p++){ accx[p] = bx; accy[p] = by; }
  #pragma unroll 4
  for (int j = 0; j < 128; j++) {
    float2 w = __ldg(&w2[(size_t)j*131072 + m2]);
    unsigned long long wx = pk2_(w.x, w.x), wy = pk2_(w.y, w.y);
    #pragma unroll
    for (int p = 0; p < 8; p++) {
      unsigned long long hpair = hp[p*128 + j];
      asm("fma.rn.f32x2 %0, %1, %2, %3;" : "=l"(accx[p]) : "l"(hpair), "l"(wx), "l"(accx[p]));
      asm("fma.rn.f32x2 %0, %1, %2, %3;" : "=l"(accy[p]) : "l"(hpair), "l"(wy), "l"(accy[p]));
    }
  }
  float2* o2 = (float2*)out;
  #pragma unroll
  for (int p = 0; p < 8; p++) {
    float2 v0, v1;
    v0.x = __uint_as_float((unsigned int)accx[p]);
    v0.y = __uint_as_float((unsigned int)accy[p]);
    v1.x = __uint_as_float((unsigned int)(accx[p] >> 32));
    v1.y = __uint_as_float((unsigned int)(accy[p] >> 32));
    o2[(size_t)(2*p)*131072 + m2]   = v0;
    o2[(size_t)(2*p+1)*131072 + m2] = v1;
  }
}

// ---------------- launcher ----------------
static void encode_pass(const float* xin,
    const float* w_enc, const float* b_enc,
    const float* wq, const float* bq, const float* wk, const float* bk,
    const float* wv, const float* bv,
    const float* W_ii, const float* W_ig, const float* W_io,
    const float* w_fc, const float* b_fc,
    unsigned int key, float* z, float* kl)
{
  hid_kernel<<<64, 256>>>(xin, w_enc, b_enc);
  heads_kernel<<<256, 256>>>(wq, bq, wk, bk, wv, bv);
  attn_kernel<<<256, 256>>>();
  combine_kernel<<<256, 256>>>();
  gates_kernel<<<192, 256>>>(W_ii, W_ig, W_io);
  reduce_kernel<<<24, 256>>>();
  lstm_kernel<<<8, 256>>>();
  fc_kernel<<<16, 256>>>(w_fc, b_fc);
  kl_kernel<<<1, 256>>>(key, z, kl);
}

extern "C" void kernel_launch(void* const* d_in, const int* in_sizes, int n_in,
                              void* d_out, int out_size)
{
  (void)in_sizes; (void)n_in; (void)out_size;
  const float* x     = (const float*)d_in[0];
  const float* w_enc = (const float*)d_in[1];
  const float* b_enc = (const float*)d_in[2];
  const float* wq    = (const float*)d_in[3];
  const float* bq    = (const float*)d_in[4];
  const float* wk    = (const float*)d_in[5];
  const float* bk    = (const float*)d_in[6];
  const float* wv    = (const float*)d_in[7];
  const float* bv    = (const float*)d_in[8];
  const float* W_ii  = (const float*)d_in[9];
  const float* W_ig  = (const float*)d_in[13];
  const float* W_io  = (const float*)d_in[15];
  const float* w_fc  = (const float*)d_in[17];
  const float* b_fc  = (const float*)d_in[18];
  const float* w_d1  = (const float*)d_in[19];
  const float* b_d1  = (const float*)d_in[20];
  const float* w_d2  = (const float*)d_in[21];
  const float* b_d2  = (const float*)d_in[22];
  const float* w_d3  = (const float*)d_in[23];
  const float* b_d3  = (const float*)d_in[24];

  float* outp = (float*)d_out;
  float* xhat = outp;                  // [16,64,32,128] = 4194304
  float* z1   = outp + 4194304;        // [16,128]
  float* z2   = z1 + 2048;             // [16,128]
  float* kl1  = z2 + 2048;             // scalar
  float* kl2  = kl1 + 1;               // scalar

  // -------- pass 1: encode(x, key=1) --------
  encode_pass(x, w_enc, b_enc, wq, bq, wk, bk, wv, bv,
              W_ii, W_ig, W_io, w_fc, b_fc, 1u, z1, kl1);
  // -------- decode(z1) --------
  dec_small_kernel<<<1, 256>>>(z1, w_d1, b_d1, w_d2, b_d2);
  big_kernel<<<512, 256>>>(w_d3, b_d3, xhat);
  // -------- pass 2: encode(x_hat1, key=2) --------
  encode_pass(xhat, w_enc, b_enc, wq, bq, wk, bk, wv, bv,
              W_ii, W_ig, W_io, w_fc, b_fc, 2u, z2, kl2);
}